// round 15
// baseline (speedup 1.0000x reference)
#include <cuda_runtime.h>
#include <cstdint>

#define NSEQ 1024
#define NRES 768
#define CM   64

// scratch
__device__ float g_wa[NRES * CM];                // weighted_avg per column
__device__ float g_kv[(size_t)NRES * NSEQ * 16]; // [r][s][0..7]=k, [8..15]=v
__device__ float g_xn[(size_t)NSEQ * NRES * CM]; // tf32-rounded LN(act), [S,R,C]
__device__ float g_mskd[NRES * NSEQ];            // mask transposed [r][s]
__device__ float g_qsp[NRES * 8 * 64];           // partial masked sums per s-tile
__device__ float g_msp[NRES * 8];                // partial mask sums per s-tile
__device__ float g_gwf[4096];                    // fragment-packed tf32 gating_w
__device__ float g_owf[4096];                    // fragment-packed tf32 output_w

__device__ __forceinline__ void fma4(float4& a, float s, const float4 w) {
    a.x += s * w.x; a.y += s * w.y; a.z += s * w.z; a.w += s * w.w;
}
__device__ __forceinline__ uint32_t f2tf32(float f) {
    uint32_t r;
    asm("cvt.rna.tf32.f32 %0, %1;" : "=r"(r) : "f"(f));
    return r;
}
__device__ __forceinline__ void mma_tf32(float4& d,
    uint32_t a0, uint32_t a1, uint32_t a2, uint32_t a3,
    uint32_t b0, uint32_t b1) {
    asm volatile("mma.sync.aligned.m16n8k8.row.col.f32.tf32.tf32.f32 "
        "{%0,%1,%2,%3}, {%4,%5,%6,%7}, {%8,%9}, {%0,%1,%2,%3};"
        : "+f"(d.x), "+f"(d.y), "+f"(d.z), "+f"(d.w)
        : "r"(a0), "r"(a1), "r"(a2), "r"(a3), "r"(b0), "r"(b1));
}
__device__ __forceinline__ float sigf(float x) {
    return __fdividef(1.f, 1.f + __expf(-x));
}
__device__ __forceinline__ uint32_t su32(const void* p) {
    return (uint32_t)__cvta_generic_to_shared(p);
}
__device__ __forceinline__ void cpasync16(uint32_t dst, const void* src) {
    asm volatile("cp.async.cg.shared.global [%0], [%1], 16;" :: "r"(dst), "l"(src));
}
#define CP_COMMIT() asm volatile("cp.async.commit_group;")
#define CP_WAIT0()  asm volatile("cp.async.wait_group 0;")

// ---------------------------------------------------------------------------
// Kernel 0: one-shot weight fragment packing. grid = 16, 256 threads.
// ---------------------------------------------------------------------------
__global__ void msa_k0(const float* __restrict__ gating_w,
                       const float* __restrict__ output_w) {
    const int i = blockIdx.x * 256 + threadIdx.x;   // 0..4095
    const int c = i >> 6, j = i & 63;
    const int kk = c >> 3, tt = c & 7;
    const int nn = j >> 3, gg = j & 7;
    const int off = ((nn * 8 + kk) * 32 + gg * 4 + (tt & 3)) * 2 + (tt >> 2);
    g_gwf[off] = __uint_as_float(f2tf32(gating_w[i]));
    g_owf[off] = __uint_as_float(f2tf32(output_w[i]));
}

// ---------------------------------------------------------------------------
// Kernel 1a: LN + K/V projection + XN writeback. Block = 8 cols x 128 rows.
// grid = (96, 8), 256 threads, occupancy 2. (R12 measured version.)
// ---------------------------------------------------------------------------
#define RST 68

__global__ void __launch_bounds__(256, 2) msa_k1a(
    const float* __restrict__ act,      // [S, R, C]
    const float* __restrict__ mask,     // [S, R]
    const float* __restrict__ ln_scale, const float* __restrict__ ln_bias,
    const float* __restrict__ key_w,    // [64, 8]
    const float* __restrict__ value_w)  // [64, 8]
{
    extern __shared__ float smk[];
    float* xch = smk;            // 17408 : x -> xn(tf32) in place
    float* mch = xch + 17408;    // 256
    float* kws = mch + 256;      // 512
    float* vws = kws + 512;      // 512
    float* scl = vws + 512;      // 64
    float* bia = scl + 64;       // 64

    const int tid  = threadIdx.x;
    const int r0   = blockIdx.x * 8;
    const int ty   = blockIdx.y;
    const int s0   = ty * 128;
    const int w    = tid >> 5, lane = tid & 31;
    const int srl  = tid >> 3;      // compute row within chunk (0..31)
    const int cc   = tid & 7;       // compute column

    for (int i = tid; i < 512; i += 256) { kws[i] = key_w[i]; vws[i] = value_w[i]; }
    if (tid < 64) { scl[tid] = ln_scale[tid]; bia[tid] = ln_bias[tid]; }
    __syncthreads();

    const float4* kw4 = (const float4*)kws;
    const float4* vw4 = (const float4*)vws;
    const uint32_t xba = su32(xch);

    float q0 = 0.f, q1 = 0.f, msum = 0.f;   // warp w owns column w; lane owns ch 2l,2l+1

    for (int cs = 0; cs < 4; ++cs) {
        const int sb = s0 + cs * 32;

        // ---- stage via cp.async: 32 rows x 2KB contiguous ----
#pragma unroll
        for (int round = 0; round < 16; ++round) {
            const int j = round * 256 + tid;
            const int sr = j >> 7, f = j & 127;
            cpasync16(xba + ((sr * 8 + (f >> 4)) * RST + (f & 15) * 4) * 4,
                      act + ((size_t)(sb + sr) * NRES + r0) * CM + f * 4);
        }
        CP_COMMIT();
        mch[tid] = mask[(size_t)(sb + srl) * NRES + r0 + cc];
        CP_WAIT0();
        __syncthreads();

        // ---- compute: one thread per (s,c) row; LN + K/V; zero shuffles ----
        {
            float4* row4 = (float4*)(xch + (srl * 8 + cc) * RST);
            float sum = 0.f, ss = 0.f;
#pragma unroll
            for (int i = 0; i < 16; i++) {
                const float4 t = row4[i];
                sum += t.x + t.y + t.z + t.w;
                ss  += t.x*t.x + t.y*t.y + t.z*t.z + t.w*t.w;
            }
            const float mu = sum * (1.f / 64.f);
            const float var = ss * (1.f / 64.f) - mu * mu;
            const float rstd = rsqrtf(var + 1e-5f);

            float4 k0 = {0,0,0,0}, k1 = {0,0,0,0}, v0 = {0,0,0,0}, v1 = {0,0,0,0};
#pragma unroll
            for (int i = 0; i < 16; i++) {
                const float4 t = row4[i];
                float4 xn;
                xn.x = (t.x - mu) * rstd * scl[i*4+0] + bia[i*4+0];
                xn.y = (t.y - mu) * rstd * scl[i*4+1] + bia[i*4+1];
                xn.z = (t.z - mu) * rstd * scl[i*4+2] + bia[i*4+2];
                xn.w = (t.w - mu) * rstd * scl[i*4+3] + bia[i*4+3];
                fma4(k0, xn.x, kw4[(i*4+0)*2]); fma4(k1, xn.x, kw4[(i*4+0)*2+1]);
                fma4(v0, xn.x, vw4[(i*4+0)*2]); fma4(v1, xn.x, vw4[(i*4+0)*2+1]);
                fma4(k0, xn.y, kw4[(i*4+1)*2]); fma4(k1, xn.y, kw4[(i*4+1)*2+1]);
                fma4(v0, xn.y, vw4[(i*4+1)*2]); fma4(v1, xn.y, vw4[(i*4+1)*2+1]);
                fma4(k0, xn.z, kw4[(i*4+2)*2]); fma4(k1, xn.z, kw4[(i*4+2)*2+1]);
                fma4(v0, xn.z, vw4[(i*4+2)*2]); fma4(v1, xn.z, vw4[(i*4+2)*2+1]);
                fma4(k0, xn.w, kw4[(i*4+3)*2]); fma4(k1, xn.w, kw4[(i*4+3)*2+1]);
                fma4(v0, xn.w, vw4[(i*4+3)*2]); fma4(v1, xn.w, vw4[(i*4+3)*2+1]);
                xn.x = __uint_as_float(f2tf32(xn.x));
                xn.y = __uint_as_float(f2tf32(xn.y));
                xn.z = __uint_as_float(f2tf32(xn.z));
                xn.w = __uint_as_float(f2tf32(xn.w));
                row4[i] = xn;
            }
            float4* dst = (float4*)(g_kv + ((size_t)(r0 + cc) * NSEQ + sb + srl) * 16);
            dst[0] = k0; dst[1] = k1; dst[2] = v0; dst[3] = v1;
        }
        __syncthreads();

        // ---- XN writeback: coalesced 2KB rows ----
#pragma unroll
        for (int round = 0; round < 16; ++round) {
            const int j = round * 256 + tid;
            const int sr = j >> 7, f = j & 127;
            const float4 t = *(const float4*)(xch + (sr * 8 + (f >> 4)) * RST + (f & 15) * 4);
            ((float4*)(g_xn + ((size_t)(sb + sr) * NRES + r0) * CM))[f] = t;
        }

        // ---- qsum pass: warp w owns column w; lane owns channels 2l,2l+1 ----
        for (int sr = 0; sr < 32; ++sr) {
            const float mm = mch[sr * 8 + w];
            const float2 x2 = *(const float2*)(xch + (sr * 8 + w) * RST + 2 * lane);
            q0 += mm * x2.x;  q1 += mm * x2.y;
            msum += (lane == 0 ? mm : 0.f);
        }
        g_mskd[(r0 + w) * NSEQ + sb + lane] = mch[lane * 8 + w];
        __syncthreads();
    }

    *(float2*)(g_qsp + ((size_t)(r0 + w) * 8 + ty) * 64 + 2 * lane) = make_float2(q0, q1);
    if (lane == 0) g_msp[(r0 + w) * 8 + ty] = msum;
}

// ---------------------------------------------------------------------------
// Kernel 1b: softmax attention for one column. grid = 768, 256 threads.
// ---------------------------------------------------------------------------
__global__ void __launch_bounds__(256, 2) msa_k1b(
    const float* __restrict__ query_w)  // [64, 64]
{
    extern __shared__ float sm[];
    float* ks   = sm;              // 8192
    float* vs   = ks + 8192;       // 8192
    float* lsm  = vs + 8192;       // 8192
    float* msk  = lsm + 8192;      // 1024
    float* qsum = msk + 1024;      // 64
    float* qf   = qsum + 64;       // 64
    float* red  = qf + 64;         // 64
    float* gmax = red + 64;        // 8
    float* invZ = gmax + 8;        // 8
    float* part = invZ + 8;        // 256
    float* Msum = part + 256;      // 1   -> 26065 floats

    const int tid  = threadIdx.x;
    const int r    = blockIdx.x;
    const int lane = tid & 31;
    const int w    = tid >> 5;

    const float4* kv4 = (const float4*)(g_kv + (size_t)r * NSEQ * 16);
    float4* ks4 = (float4*)ks;
    float4* vs4 = (float4*)vs;
    for (int i = tid; i < 4096; i += 256) {
        const int s = i >> 2, q = i & 3;
        const float4 v = kv4[i];
        if (q < 2) ks4[s * 2 + q] = v;
        else       vs4[s * 2 + (q - 2)] = v;
    }
    for (int i = tid; i < 1024; i += 256) msk[i] = g_mskd[r * NSEQ + i];
    if (tid < 64) {
        float a = 0.f;
#pragma unroll
        for (int t = 0; t < 8; t++) a += g_qsp[((size_t)r * 8 + t) * 64 + tid];
        qsum[tid] = a;
    }
    if (tid == 64) {
        float a = 0.f;
#pragma unroll
        for (int t = 0; t < 8; t++) a += g_msp[r * 8 + t];
        *Msum = a;
    }
    __syncthreads();

    if (tid < 64) {
        const float invM = 1.f / (*Msum + 1e-10f);
        float acc = 0.f;
        for (int c = 0; c < 64; c++) acc += qsum[c] * query_w[c * 64 + tid];
        qf[tid] = acc * invM * 0.35355339059327373f;
    }
    __syncthreads();

    float lmax[8];
#pragma unroll
    for (int h = 0; h < 8; h++) lmax[h] = -3.4e38f;
#pragma unroll
    for (int it = 0; it < 4; it++) {
        const int s = tid + it * 256;
        const float4* kp = (const float4*)(ks + s * 8);
        const float4 k0 = kp[0], k1 = kp[1];
        const float b = 1e9f * (msk[s] - 1.f);
#pragma unroll
        for (int h = 0; h < 8; h++) {
            const float* q = qf + h * 8;
            float l = b + q[0]*k0.x + q[1]*k0.y + q[2]*k0.z + q[3]*k0.w
                        + q[4]*k1.x + q[5]*k1.y + q[6]*k1.z + q[7]*k1.w;
            lsm[s * 8 + h] = l;
            lmax[h] = fmaxf(lmax[h], l);
        }
    }
#pragma unroll
    for (int h = 0; h < 8; h++) {
#pragma unroll
        for (int off = 16; off; off >>= 1)
            lmax[h] = fmaxf(lmax[h], __shfl_xor_sync(0xffffffffu, lmax[h], off));
    }
    if (lane == 0) {
#pragma unroll
        for (int h = 0; h < 8; h++) red[w * 8 + h] = lmax[h];
    }
    __syncthreads();
    if (tid < 8) {
        float mm = red[tid];
#pragma unroll
        for (int ww = 1; ww < 8; ww++) mm = fmaxf(mm, red[ww * 8 + tid]);
        gmax[tid] = mm;
    }
    __syncthreads();

    float zl[8];
#pragma unroll
    for (int h = 0; h < 8; h++) zl[h] = 0.f;
#pragma unroll
    for (int it = 0; it < 4; it++) {
        const int s = tid + it * 256;
#pragma unroll
        for (int h = 0; h < 8; h++) {
            const float e = __expf(lsm[s * 8 + h] - gmax[h]);
            lsm[s * 8 + h] = e;
            zl[h] += e;
        }
    }
#pragma unroll
    for (int h = 0; h < 8; h++) {
#pragma unroll
        for (int off = 16; off; off >>= 1)
            zl[h] += __shfl_xor_sync(0xffffffffu, zl[h], off);
    }
    if (lane == 0) {
#pragma unroll
        for (int h = 0; h < 8; h++) red[w * 8 + h] = zl[h];
    }
    __syncthreads();
    if (tid < 8) {
        float z = 0.f;
#pragma unroll
        for (int ww = 0; ww < 8; ww++) z += red[ww * 8 + tid];
        invZ[tid] = 1.f / z;
    }
    __syncthreads();

    {
        const int hd = tid & 63, q4 = tid >> 6;
        const int h = hd >> 3, d = hd & 7;
        float p = 0.f;
        const int sb = q4 * 256;
        for (int s = sb; s < sb + 256; ++s)
            p += lsm[s * 8 + h] * vs[s * 8 + d];
        part[tid] = p;
    }
    __syncthreads();
    if (tid < 64) {
        const int h = tid >> 3;
        g_wa[r * 64 + tid] =
            (part[tid] + part[tid + 64] + part[tid + 128] + part[tid + 192]) * invZ[h];
    }
}

// ---------------------------------------------------------------------------
// Kernel 2: gate + output via tf32 MMA. 128-row tiles, occupancy 3;
// B fragments read directly from global (L1/L2-resident) — no smem staging.
// grid = (768, 8), 256 threads, warp owns one 16-row strip.
// ---------------------------------------------------------------------------
#define XS 68

__global__ void __launch_bounds__(256, 3) msa_k2(
    const float* __restrict__ gating_b,  // [64]
    const float* __restrict__ output_b,  // [64]
    float* __restrict__ out)             // [S, R, C]
{
    extern __shared__ float sm2[];
    float* xnf = sm2;              // 128 rows * 68 = 8704
    float* was = xnf + 8704;       // 64
    float* gbs = was + 64;         // 64
    float* obs = gbs + 64;         // 64

    const int tid  = threadIdx.x;
    const int r    = blockIdx.x;
    const int s0   = blockIdx.y * 128;
    const int w    = tid >> 5, lane = tid & 31;
    const int c4   = lane & 15, rsel = lane >> 4;
    const int g    = lane >> 2, t = lane & 3;

    // ---- stage xn tile via cp.async ----
    const uint32_t xba = su32(xnf);
#pragma unroll
    for (int rnd = 0; rnd < 8; rnd++) {
        const int j = rnd * 256 + tid;        // float4 idx 0..2047
        const int row = j >> 4, f = j & 15;
        cpasync16(xba + (row * XS + f * 4) * 4,
                  g_xn + ((size_t)(s0 + row) * NRES + r) * CM + f * 4);
    }
    CP_COMMIT();

    if (tid < 64) {
        was[tid] = g_wa[r * 64 + tid];
        gbs[tid] = gating_b[tid];  obs[tid] = output_b[tid];
    }
    CP_WAIT0();
    __syncthreads();

    float* st0 = xnf + (w * 16) * XS;   // warp-private 16-row strip
    const float2* gw2 = (const float2*)g_gwf;
    const float2* ow2 = (const float2*)g_owf;

    // ---- GEMM1: logits = XN @ GW ----
    float4 acc0[8];
#pragma unroll
    for (int n = 0; n < 8; n++) acc0[n] = make_float4(0.f, 0.f, 0.f, 0.f);
#pragma unroll
    for (int k = 0; k < 8; k++) {
        const int kc = k * 8 + t;
        const uint32_t a00 = __float_as_uint(st0[g * XS + kc]);
        const uint32_t a01 = __float_as_uint(st0[(g + 8) * XS + kc]);
        const uint32_t a02 = __float_as_uint(st0[g * XS + kc + 4]);
        const uint32_t a03 = __float_as_uint(st0[(g + 8) * XS + kc + 4]);
#pragma unroll
        for (int n = 0; n < 8; n++) {
            const float2 b = __ldg(gw2 + (n * 8 + k) * 32 + lane);
            mma_tf32(acc0[n], a00, a01, a02, a03,
                     __float_as_uint(b.x), __float_as_uint(b.y));
        }
    }
    __syncwarp();

    // ---- gate: G = wa*sigmoid(logit+gb) ----
#pragma unroll
    for (int n = 0; n < 8; n++) {
        const int c0 = n * 8 + 2 * t;
        const float w0 = was[c0], w1 = was[c0 + 1];
        const float b0 = gbs[c0], b1 = gbs[c0 + 1];
        float2 p;
        p.x = __uint_as_float(f2tf32(w0 * sigf(acc0[n].x + b0)));
        p.y = __uint_as_float(f2tf32(w1 * sigf(acc0[n].y + b1)));
        *(float2*)(st0 + g * XS + c0) = p;
        p.x = __uint_as_float(f2tf32(w0 * sigf(acc0[n].z + b0)));
        p.y = __uint_as_float(f2tf32(w1 * sigf(acc0[n].w + b1)));
        *(float2*)(st0 + (g + 8) * XS + c0) = p;
    }
    __syncwarp();

    // ---- GEMM2: OUT = G @ OW + ob ----
    float4 o0[8];
#pragma unroll
    for (int n = 0; n < 8; n++) {
        const int c0 = n * 8 + 2 * t;
        o0[n] = make_float4(obs[c0], obs[c0+1], obs[c0], obs[c0+1]);
    }
#pragma unroll
    for (int k = 0; k < 8; k++) {
        const int kc = k * 8 + t;
        const uint32_t a00 = __float_as_uint(st0[g * XS + kc]);
        const uint32_t a01 = __float_as_uint(st0[(g + 8) * XS + kc]);
        const uint32_t a02 = __float_as_uint(st0[g * XS + kc + 4]);
        const uint32_t a03 = __float_as_uint(st0[(g + 8) * XS + kc + 4]);
#pragma unroll
        for (int n = 0; n < 8; n++) {
            const float2 b = __ldg(ow2 + (n * 8 + k) * 32 + lane);
            mma_tf32(o0[n], a00, a01, a02, a03,
                     __float_as_uint(b.x), __float_as_uint(b.y));
        }
    }
    __syncwarp();

    // ---- stage outputs row-major ----
#pragma unroll
    for (int n = 0; n < 8; n++) {
        const int c0 = n * 8 + 2 * t;
        *(float2*)(st0 + g * XS + c0)       = make_float2(o0[n].x, o0[n].y);
        *(float2*)(st0 + (g + 8) * XS + c0) = make_float2(o0[n].z, o0[n].w);
    }
    __syncwarp();

    // ---- coalesced STG ----
#pragma unroll
    for (int rnd = 0; rnd < 8; rnd++) {
        const int row = w * 16 + rnd * 2 + rsel;
        const float4 v = *(const float4*)(xnf + row * XS + c4 * 4);
        *(float4*)(out + ((size_t)(s0 + row) * NRES + r) * CM + c4 * 4) = v;
    }
}

// ---------------------------------------------------------------------------
#define K1A_SMEM (18816 * 4)
#define K1B_SMEM (26065 * 4)
#define K2_SMEM  (8896 * 4)

extern "C" void kernel_launch(void* const* d_in, const int* in_sizes, int n_in,
                              void* d_out, int out_size) {
    (void)in_sizes; (void)n_in; (void)out_size;
    const float* act      = (const float*)d_in[0];
    const float* mask     = (const float*)d_in[1];
    const float* ln_scale = (const float*)d_in[2];
    const float* ln_bias  = (const float*)d_in[3];
    const float* query_w  = (const float*)d_in[4];
    const float* key_w    = (const float*)d_in[5];
    const float* value_w  = (const float*)d_in[6];
    const float* gating_w = (const float*)d_in[7];
    const float* gating_b = (const float*)d_in[8];
    const float* output_w = (const float*)d_in[9];
    const float* output_b = (const float*)d_in[10];
    float* out = (float*)d_out;

    cudaFuncSetAttribute(msa_k1a, cudaFuncAttributeMaxDynamicSharedMemorySize, K1A_SMEM);
    cudaFuncSetAttribute(msa_k1b, cudaFuncAttributeMaxDynamicSharedMemorySize, K1B_SMEM);
    cudaFuncSetAttribute(msa_k2,  cudaFuncAttributeMaxDynamicSharedMemorySize, K2_SMEM);

    msa_k0<<<16, 256>>>(gating_w, output_w);
    msa_k1a<<<dim3(96, 8), 256, K1A_SMEM>>>(act, mask, ln_scale, ln_bias, key_w, value_w);
    msa_k1b<<<NRES, 256, K1B_SMEM>>>(query_w);
    msa_k2<<<dim3(NRES, 8), 256, K2_SMEM>>>(gating_b, output_b, out);
}

// round 16
// speedup vs baseline: 1.0724x; 1.0724x over previous
#include <cuda_runtime.h>
#include <cstdint>

#define NSEQ 1024
#define NRES 768
#define CM   64

// scratch
__device__ float g_wa[NRES * CM];                // weighted_avg per column
__device__ float g_kv[(size_t)NRES * NSEQ * 16]; // [r][s][0..7]=k, [8..15]=v
__device__ float g_xn[(size_t)NSEQ * NRES * CM]; // tf32-rounded LN(act), [S,R,C]
__device__ float g_mskd[NRES * NSEQ];            // mask transposed [r][s]
__device__ float g_qsp[NRES * 8 * 64];           // partial masked sums per s-tile
__device__ float g_msp[NRES * 8];                // partial mask sums per s-tile
__device__ float g_gwf[4096];                    // fragment-packed tf32 gating_w
__device__ float g_owf[4096];                    // fragment-packed tf32 output_w

__device__ __forceinline__ void fma4(float4& a, float s, const float4 w) {
    a.x += s * w.x; a.y += s * w.y; a.z += s * w.z; a.w += s * w.w;
}
__device__ __forceinline__ uint32_t f2tf32(float f) {
    uint32_t r;
    asm("cvt.rna.tf32.f32 %0, %1;" : "=r"(r) : "f"(f));
    return r;
}
__device__ __forceinline__ void mma_tf32(float4& d,
    uint32_t a0, uint32_t a1, uint32_t a2, uint32_t a3,
    uint32_t b0, uint32_t b1) {
    asm volatile("mma.sync.aligned.m16n8k8.row.col.f32.tf32.tf32.f32 "
        "{%0,%1,%2,%3}, {%4,%5,%6,%7}, {%8,%9}, {%0,%1,%2,%3};"
        : "+f"(d.x), "+f"(d.y), "+f"(d.z), "+f"(d.w)
        : "r"(a0), "r"(a1), "r"(a2), "r"(a3), "r"(b0), "r"(b1));
}
__device__ __forceinline__ float sigf(float x) {
    return __fdividef(1.f, 1.f + __expf(-x));
}
__device__ __forceinline__ uint32_t su32(const void* p) {
    return (uint32_t)__cvta_generic_to_shared(p);
}
__device__ __forceinline__ void cpasync16(uint32_t dst, const void* src) {
    asm volatile("cp.async.cg.shared.global [%0], [%1], 16;" :: "r"(dst), "l"(src));
}
#define CP_COMMIT() asm volatile("cp.async.commit_group;")
#define CP_WAIT0()  asm volatile("cp.async.wait_group 0;")

// ---------------------------------------------------------------------------
// Kernel 0: one-shot weight fragment packing. grid = 16, 256 threads.
// ---------------------------------------------------------------------------
__global__ void msa_k0(const float* __restrict__ gating_w,
                       const float* __restrict__ output_w) {
    const int i = blockIdx.x * 256 + threadIdx.x;   // 0..4095
    const int c = i >> 6, j = i & 63;
    const int kk = c >> 3, tt = c & 7;
    const int nn = j >> 3, gg = j & 7;
    const int off = ((nn * 8 + kk) * 32 + gg * 4 + (tt & 3)) * 2 + (tt >> 2);
    g_gwf[off] = __uint_as_float(f2tf32(gating_w[i]));
    g_owf[off] = __uint_as_float(f2tf32(output_w[i]));
}

// ---------------------------------------------------------------------------
// Kernel 1a: LN + K/V projection + XN writeback. Block = 8 cols x 128 rows.
// grid = (96, 8), 256 threads, occupancy 2. (R12 measured version.)
// ---------------------------------------------------------------------------
#define RST 68

__global__ void __launch_bounds__(256, 2) msa_k1a(
    const float* __restrict__ act,      // [S, R, C]
    const float* __restrict__ mask,     // [S, R]
    const float* __restrict__ ln_scale, const float* __restrict__ ln_bias,
    const float* __restrict__ key_w,    // [64, 8]
    const float* __restrict__ value_w)  // [64, 8]
{
    extern __shared__ float smk[];
    float* xch = smk;            // 17408 : x -> xn(tf32) in place
    float* mch = xch + 17408;    // 256
    float* kws = mch + 256;      // 512
    float* vws = kws + 512;      // 512
    float* scl = vws + 512;      // 64
    float* bia = scl + 64;       // 64

    const int tid  = threadIdx.x;
    const int r0   = blockIdx.x * 8;
    const int ty   = blockIdx.y;
    const int s0   = ty * 128;
    const int w    = tid >> 5, lane = tid & 31;
    const int srl  = tid >> 3;      // compute row within chunk (0..31)
    const int cc   = tid & 7;       // compute column

    for (int i = tid; i < 512; i += 256) { kws[i] = key_w[i]; vws[i] = value_w[i]; }
    if (tid < 64) { scl[tid] = ln_scale[tid]; bia[tid] = ln_bias[tid]; }
    __syncthreads();

    const float4* kw4 = (const float4*)kws;
    const float4* vw4 = (const float4*)vws;
    const uint32_t xba = su32(xch);

    float q0 = 0.f, q1 = 0.f, msum = 0.f;   // warp w owns column w; lane owns ch 2l,2l+1

    for (int cs = 0; cs < 4; ++cs) {
        const int sb = s0 + cs * 32;

        // ---- stage via cp.async: 32 rows x 2KB contiguous ----
#pragma unroll
        for (int round = 0; round < 16; ++round) {
            const int j = round * 256 + tid;
            const int sr = j >> 7, f = j & 127;
            cpasync16(xba + ((sr * 8 + (f >> 4)) * RST + (f & 15) * 4) * 4,
                      act + ((size_t)(sb + sr) * NRES + r0) * CM + f * 4);
        }
        CP_COMMIT();
        mch[tid] = mask[(size_t)(sb + srl) * NRES + r0 + cc];
        CP_WAIT0();
        __syncthreads();

        // ---- compute: one thread per (s,c) row; LN + K/V; zero shuffles ----
        {
            float4* row4 = (float4*)(xch + (srl * 8 + cc) * RST);
            float sum = 0.f, ss = 0.f;
#pragma unroll
            for (int i = 0; i < 16; i++) {
                const float4 t = row4[i];
                sum += t.x + t.y + t.z + t.w;
                ss  += t.x*t.x + t.y*t.y + t.z*t.z + t.w*t.w;
            }
            const float mu = sum * (1.f / 64.f);
            const float var = ss * (1.f / 64.f) - mu * mu;
            const float rstd = rsqrtf(var + 1e-5f);

            float4 k0 = {0,0,0,0}, k1 = {0,0,0,0}, v0 = {0,0,0,0}, v1 = {0,0,0,0};
#pragma unroll
            for (int i = 0; i < 16; i++) {
                const float4 t = row4[i];
                float4 xn;
                xn.x = (t.x - mu) * rstd * scl[i*4+0] + bia[i*4+0];
                xn.y = (t.y - mu) * rstd * scl[i*4+1] + bia[i*4+1];
                xn.z = (t.z - mu) * rstd * scl[i*4+2] + bia[i*4+2];
                xn.w = (t.w - mu) * rstd * scl[i*4+3] + bia[i*4+3];
                fma4(k0, xn.x, kw4[(i*4+0)*2]); fma4(k1, xn.x, kw4[(i*4+0)*2+1]);
                fma4(v0, xn.x, vw4[(i*4+0)*2]); fma4(v1, xn.x, vw4[(i*4+0)*2+1]);
                fma4(k0, xn.y, kw4[(i*4+1)*2]); fma4(k1, xn.y, kw4[(i*4+1)*2+1]);
                fma4(v0, xn.y, vw4[(i*4+1)*2]); fma4(v1, xn.y, vw4[(i*4+1)*2+1]);
                fma4(k0, xn.z, kw4[(i*4+2)*2]); fma4(k1, xn.z, kw4[(i*4+2)*2+1]);
                fma4(v0, xn.z, vw4[(i*4+2)*2]); fma4(v1, xn.z, vw4[(i*4+2)*2+1]);
                fma4(k0, xn.w, kw4[(i*4+3)*2]); fma4(k1, xn.w, kw4[(i*4+3)*2+1]);
                fma4(v0, xn.w, vw4[(i*4+3)*2]); fma4(v1, xn.w, vw4[(i*4+3)*2+1]);
                xn.x = __uint_as_float(f2tf32(xn.x));
                xn.y = __uint_as_float(f2tf32(xn.y));
                xn.z = __uint_as_float(f2tf32(xn.z));
                xn.w = __uint_as_float(f2tf32(xn.w));
                row4[i] = xn;
            }
            float4* dst = (float4*)(g_kv + ((size_t)(r0 + cc) * NSEQ + sb + srl) * 16);
            dst[0] = k0; dst[1] = k1; dst[2] = v0; dst[3] = v1;
        }
        __syncthreads();

        // ---- XN writeback: coalesced 2KB rows ----
#pragma unroll
        for (int round = 0; round < 16; ++round) {
            const int j = round * 256 + tid;
            const int sr = j >> 7, f = j & 127;
            const float4 t = *(const float4*)(xch + (sr * 8 + (f >> 4)) * RST + (f & 15) * 4);
            ((float4*)(g_xn + ((size_t)(sb + sr) * NRES + r0) * CM))[f] = t;
        }

        // ---- qsum pass: warp w owns column w; lane owns channels 2l,2l+1 ----
        for (int sr = 0; sr < 32; ++sr) {
            const float mm = mch[sr * 8 + w];
            const float2 x2 = *(const float2*)(xch + (sr * 8 + w) * RST + 2 * lane);
            q0 += mm * x2.x;  q1 += mm * x2.y;
            msum += (lane == 0 ? mm : 0.f);
        }
        g_mskd[(r0 + w) * NSEQ + sb + lane] = mch[lane * 8 + w];
        __syncthreads();
    }

    *(float2*)(g_qsp + ((size_t)(r0 + w) * 8 + ty) * 64 + 2 * lane) = make_float2(q0, q1);
    if (lane == 0) g_msp[(r0 + w) * 8 + ty] = msum;
}

// ---------------------------------------------------------------------------
// Kernel 1b: softmax attention for one column. grid = 768, 512 threads.
// ---------------------------------------------------------------------------
__global__ void __launch_bounds__(512, 2) msa_k1b(
    const float* __restrict__ query_w)  // [64, 64]
{
    extern __shared__ float sm[];
    float* ks   = sm;              // 8192
    float* vs   = ks + 8192;       // 8192
    float* lsm  = vs + 8192;       // 8192
    float* msk  = lsm + 8192;      // 1024
    float* qsum = msk + 1024;      // 64
    float* qf   = qsum + 64;       // 64
    float* red  = qf + 64;         // 128  (16 warps x 8 heads)
    float* gmax = red + 128;       // 8
    float* invZ = gmax + 8;        // 8
    float* part = invZ + 8;        // 512
    float* Msum = part + 512;      // 1   -> 26385 floats

    const int tid  = threadIdx.x;
    const int r    = blockIdx.x;
    const int lane = tid & 31;
    const int w    = tid >> 5;

    const float4* kv4 = (const float4*)(g_kv + (size_t)r * NSEQ * 16);
    float4* ks4 = (float4*)ks;
    float4* vs4 = (float4*)vs;
    for (int i = tid; i < 4096; i += 512) {
        const int s = i >> 2, q = i & 3;
        const float4 v = kv4[i];
        if (q < 2) ks4[s * 2 + q] = v;
        else       vs4[s * 2 + (q - 2)] = v;
    }
    for (int i = tid; i < 1024; i += 512) msk[i] = g_mskd[r * NSEQ + i];
    if (tid < 64) {
        float a = 0.f;
#pragma unroll
        for (int t = 0; t < 8; t++) a += g_qsp[((size_t)r * 8 + t) * 64 + tid];
        qsum[tid] = a;
    }
    if (tid == 64) {
        float a = 0.f;
#pragma unroll
        for (int t = 0; t < 8; t++) a += g_msp[r * 8 + t];
        *Msum = a;
    }
    __syncthreads();

    if (tid < 64) {
        const float invM = 1.f / (*Msum + 1e-10f);
        float acc = 0.f;
        for (int c = 0; c < 64; c++) acc += qsum[c] * query_w[c * 64 + tid];
        qf[tid] = acc * invM * 0.35355339059327373f;
    }
    __syncthreads();

    float lmax[8];
#pragma unroll
    for (int h = 0; h < 8; h++) lmax[h] = -3.4e38f;
#pragma unroll
    for (int it = 0; it < 2; it++) {
        const int s = tid + it * 512;
        const float4* kp = (const float4*)(ks + s * 8);
        const float4 k0 = kp[0], k1 = kp[1];
        const float b = 1e9f * (msk[s] - 1.f);
#pragma unroll
        for (int h = 0; h < 8; h++) {
            const float* q = qf + h * 8;
            float l = b + q[0]*k0.x + q[1]*k0.y + q[2]*k0.z + q[3]*k0.w
                        + q[4]*k1.x + q[5]*k1.y + q[6]*k1.z + q[7]*k1.w;
            lsm[s * 8 + h] = l;
            lmax[h] = fmaxf(lmax[h], l);
        }
    }
#pragma unroll
    for (int h = 0; h < 8; h++) {
#pragma unroll
        for (int off = 16; off; off >>= 1)
            lmax[h] = fmaxf(lmax[h], __shfl_xor_sync(0xffffffffu, lmax[h], off));
    }
    if (lane == 0) {
#pragma unroll
        for (int h = 0; h < 8; h++) red[w * 8 + h] = lmax[h];
    }
    __syncthreads();
    if (tid < 8) {
        float mm = red[tid];
#pragma unroll
        for (int ww = 1; ww < 16; ww++) mm = fmaxf(mm, red[ww * 8 + tid]);
        gmax[tid] = mm;
    }
    __syncthreads();

    float zl[8];
#pragma unroll
    for (int h = 0; h < 8; h++) zl[h] = 0.f;
#pragma unroll
    for (int it = 0; it < 2; it++) {
        const int s = tid + it * 512;
#pragma unroll
        for (int h = 0; h < 8; h++) {
            const float e = __expf(lsm[s * 8 + h] - gmax[h]);
            lsm[s * 8 + h] = e;
            zl[h] += e;
        }
    }
#pragma unroll
    for (int h = 0; h < 8; h++) {
#pragma unroll
        for (int off = 16; off; off >>= 1)
            zl[h] += __shfl_xor_sync(0xffffffffu, zl[h], off);
    }
    if (lane == 0) {
#pragma unroll
        for (int h = 0; h < 8; h++) red[w * 8 + h] = zl[h];
    }
    __syncthreads();
    if (tid < 8) {
        float z = 0.f;
#pragma unroll
        for (int ww = 0; ww < 16; ww++) z += red[ww * 8 + tid];
        invZ[tid] = 1.f / z;
    }
    __syncthreads();

    {
        const int hd = tid & 63, q8 = tid >> 6;
        const int h = hd >> 3, d = hd & 7;
        float p = 0.f;
        const int sb = q8 * 128;
        for (int s = sb; s < sb + 128; ++s)
            p += lsm[s * 8 + h] * vs[s * 8 + d];
        part[tid] = p;
    }
    __syncthreads();
    if (tid < 64) {
        const int h = tid >> 3;
        float acc = 0.f;
#pragma unroll
        for (int k = 0; k < 8; k++) acc += part[tid + 64 * k];
        g_wa[r * 64 + tid] = acc * invZ[h];
    }
}

// ---------------------------------------------------------------------------
// Kernel 2: gate + output via tf32 MMA. 256-row tiles (R12 measured, 113.6us).
// grid = (768, 4), 256 threads, warp owns two 16-row strips.
// ---------------------------------------------------------------------------
#define XS 68

__global__ void __launch_bounds__(256, 2) msa_k2(
    const float* __restrict__ gating_b,  // [64]
    const float* __restrict__ output_b,  // [64]
    float* __restrict__ out)             // [S, R, C]
{
    extern __shared__ float sm2[];
    float* xnf = sm2;              // 256 rows * 68 = 17408
    float* gwf = xnf + 17408;      // 4096
    float* owf = gwf + 4096;       // 4096
    float* was = owf + 4096;       // 64
    float* gbs = was + 64;         // 64
    float* obs = gbs + 64;         // 64

    const int tid  = threadIdx.x;
    const int r    = blockIdx.x;
    const int s0   = blockIdx.y * 256;
    const int w    = tid >> 5, lane = tid & 31;
    const int c4   = lane & 15, rsel = lane >> 4;
    const int g    = lane >> 2, t = lane & 3;

    // ---- stage xn tile + weights via cp.async ----
    const uint32_t xba = su32(xnf);
    const uint32_t gba = su32(gwf);
    const uint32_t oba = su32(owf);
#pragma unroll
    for (int rnd = 0; rnd < 16; rnd++) {
        const int j = rnd * 256 + tid;        // float4 idx 0..4095
        const int row = j >> 4, f = j & 15;
        cpasync16(xba + (row * XS + f * 4) * 4,
                  g_xn + ((size_t)(s0 + row) * NRES + r) * CM + f * 4);
    }
#pragma unroll
    for (int rnd = 0; rnd < 4; rnd++) {
        const int j = rnd * 256 + tid;        // float4 idx 0..1023
        cpasync16(gba + j * 16, g_gwf + j * 4);
        cpasync16(oba + j * 16, g_owf + j * 4);
    }
    CP_COMMIT();

    if (tid < 64) {
        was[tid] = g_wa[r * 64 + tid];
        gbs[tid] = gating_b[tid];  obs[tid] = output_b[tid];
    }
    CP_WAIT0();
    __syncthreads();

    const int rb = w * 32;
    float* st0 = xnf + rb * XS;
    float* st1 = xnf + (rb + 16) * XS;

    // ---- GEMM1: logits = XN @ GW ----
    float4 acc0[8], acc1[8];
#pragma unroll
    for (int n = 0; n < 8; n++) { acc0[n] = make_float4(0,0,0,0); acc1[n] = make_float4(0,0,0,0); }
#pragma unroll
    for (int k = 0; k < 8; k++) {
        const int kc = k * 8 + t;
        const uint32_t a00 = __float_as_uint(st0[g * XS + kc]);
        const uint32_t a01 = __float_as_uint(st0[(g + 8) * XS + kc]);
        const uint32_t a02 = __float_as_uint(st0[g * XS + kc + 4]);
        const uint32_t a03 = __float_as_uint(st0[(g + 8) * XS + kc + 4]);
        const uint32_t a10 = __float_as_uint(st1[g * XS + kc]);
        const uint32_t a11 = __float_as_uint(st1[(g + 8) * XS + kc]);
        const uint32_t a12 = __float_as_uint(st1[g * XS + kc + 4]);
        const uint32_t a13 = __float_as_uint(st1[(g + 8) * XS + kc + 4]);
#pragma unroll
        for (int n = 0; n < 8; n++) {
            const float2 b = *(const float2*)(gwf + ((n * 8 + k) * 32 + lane) * 2);
            mma_tf32(acc0[n], a00, a01, a02, a03,
                     __float_as_uint(b.x), __float_as_uint(b.y));
            mma_tf32(acc1[n], a10, a11, a12, a13,
                     __float_as_uint(b.x), __float_as_uint(b.y));
        }
    }
    __syncwarp();

    // ---- gate: G = wa*sigmoid(logit+gb) ----
#pragma unroll
    for (int n = 0; n < 8; n++) {
        const int c0 = n * 8 + 2 * t;
        const float w0 = was[c0], w1 = was[c0 + 1];
        const float b0 = gbs[c0], b1 = gbs[c0 + 1];
        float2 p;
        p.x = __uint_as_float(f2tf32(w0 * sigf(acc0[n].x + b0)));
        p.y = __uint_as_float(f2tf32(w1 * sigf(acc0[n].y + b1)));
        *(float2*)(st0 + g * XS + c0) = p;
        p.x = __uint_as_float(f2tf32(w0 * sigf(acc0[n].z + b0)));
        p.y = __uint_as_float(f2tf32(w1 * sigf(acc0[n].w + b1)));
        *(float2*)(st0 + (g + 8) * XS + c0) = p;
        p.x = __uint_as_float(f2tf32(w0 * sigf(acc1[n].x + b0)));
        p.y = __uint_as_float(f2tf32(w1 * sigf(acc1[n].y + b1)));
        *(float2*)(st1 + g * XS + c0) = p;
        p.x = __uint_as_float(f2tf32(w0 * sigf(acc1[n].z + b0)));
        p.y = __uint_as_float(f2tf32(w1 * sigf(acc1[n].w + b1)));
        *(float2*)(st1 + (g + 8) * XS + c0) = p;
    }
    __syncwarp();

    // ---- GEMM2: OUT = G @ OW + ob ----
    float4 o0[8], o1[8];
#pragma unroll
    for (int n = 0; n < 8; n++) {
        const int c0 = n * 8 + 2 * t;
        o0[n] = make_float4(obs[c0], obs[c0+1], obs[c0], obs[c0+1]);
        o1[n] = o0[n];
    }
#pragma unroll
    for (int k = 0; k < 8; k++) {
        const int kc = k * 8 + t;
        const uint32_t a00 = __float_as_uint(st0[g * XS + kc]);
        const uint32_t a01 = __float_as_uint(st0[(g + 8) * XS + kc]);
        const uint32_t a02 = __float_as_uint(st0[g * XS + kc + 4]);
        const uint32_t a03 = __float_as_uint(st0[(g + 8) * XS + kc + 4]);
        const uint32_t a10 = __float_as_uint(st1[g * XS + kc]);
        const uint32_t a11 = __float_as_uint(st1[(g + 8) * XS + kc]);
        const uint32_t a12 = __float_as_uint(st1[g * XS + kc + 4]);
        const uint32_t a13 = __float_as_uint(st1[(g + 8) * XS + kc + 4]);
#pragma unroll
        for (int n = 0; n < 8; n++) {
            const float2 b = *(const float2*)(owf + ((n * 8 + k) * 32 + lane) * 2);
            mma_tf32(o0[n], a00, a01, a02, a03,
                     __float_as_uint(b.x), __float_as_uint(b.y));
            mma_tf32(o1[n], a10, a11, a12, a13,
                     __float_as_uint(b.x), __float_as_uint(b.y));
        }
    }
    __syncwarp();

    // ---- stage outputs row-major ----
#pragma unroll
    for (int n = 0; n < 8; n++) {
        const int c0 = n * 8 + 2 * t;
        *(float2*)(st0 + g * XS + c0)       = make_float2(o0[n].x, o0[n].y);
        *(float2*)(st0 + (g + 8) * XS + c0) = make_float2(o0[n].z, o0[n].w);
        *(float2*)(st1 + g * XS + c0)       = make_float2(o1[n].x, o1[n].y);
        *(float2*)(st1 + (g + 8) * XS + c0) = make_float2(o1[n].z, o1[n].w);
    }
    __syncwarp();

    // ---- coalesced STG ----
#pragma unroll
    for (int rnd = 0; rnd < 16; rnd++) {
        const int row = w * 32 + rnd * 2 + rsel;
        const float4 v = *(const float4*)(xnf + row * XS + c4 * 4);
        *(float4*)(out + ((size_t)(s0 + row) * NRES + r) * CM + c4 * 4) = v;
    }
}

// ---------------------------------------------------------------------------
#define K1A_SMEM (18816 * 4)
#define K1B_SMEM (26385 * 4)
#define K2_SMEM  (25792 * 4)

extern "C" void kernel_launch(void* const* d_in, const int* in_sizes, int n_in,
                              void* d_out, int out_size) {
    (void)in_sizes; (void)n_in; (void)out_size;
    const float* act      = (const float*)d_in[0];
    const float* mask     = (const float*)d_in[1];
    const float* ln_scale = (const float*)d_in[2];
    const float* ln_bias  = (const float*)d_in[3];
    const float* query_w  = (const float*)d_in[4];
    const float* key_w    = (const float*)d_in[5];
    const float* value_w  = (const float*)d_in[6];
    const float* gating_w = (const float*)d_in[7];
    const float* gating_b = (const float*)d_in[8];
    const float* output_w = (const float*)d_in[9];
    const float* output_b = (const float*)d_in[10];
    float* out = (float*)d_out;

    cudaFuncSetAttribute(msa_k1a, cudaFuncAttributeMaxDynamicSharedMemorySize, K1A_SMEM);
    cudaFuncSetAttribute(msa_k1b, cudaFuncAttributeMaxDynamicSharedMemorySize, K1B_SMEM);
    cudaFuncSetAttribute(msa_k2,  cudaFuncAttributeMaxDynamicSharedMemorySize, K2_SMEM);

    msa_k0<<<16, 256>>>(gating_w, output_w);
    msa_k1a<<<dim3(96, 8), 256, K1A_SMEM>>>(act, mask, ln_scale, ln_bias, key_w, value_w);
    msa_k1b<<<NRES, 512, K1B_SMEM>>>(query_w);
    msa_k2<<<dim3(NRES, 4), 256, K2_SMEM>>>(gating_b, output_b, out);
}